// round 3
// baseline (speedup 1.0000x reference)
#include <cuda_runtime.h>
#include <cuda_bf16.h>
#include <math.h>

// ---------------- problem constants ----------------
#define BB 4
#define SS 2048
#define DD 1024
#define HH 16
#define HDIM 64
#define EE 8
#define HID 4096
#define TOPK 2
#define TT (BB*SS)          // 8192 tokens
#define NE (TT*TOPK)        // 16384 expert entries

// ---------------- scratch (device globals; no allocations) ----------------
__device__ float g_q[(size_t)TT*DD];
__device__ float g_k[(size_t)TT*DD];
__device__ float g_v[(size_t)TT*DD];
__device__ float g_att[(size_t)TT*DD];
__device__ float g_tmp[(size_t)TT*DD];
__device__ float g_x1[(size_t)TT*DD];
__device__ float g_x2[(size_t)TT*DD];
__device__ float g_hid[(size_t)NE*HID];   // 256 MiB
__device__ float g_y[(size_t)NE*DD];      // 64 MiB

__device__ int   g_cnt[EE];
__device__ int   g_base[EE];
__device__ int   g_cur[EE];
__device__ int   g_tok[NE];        // entry -> token id
__device__ int   g_te[TT*TOPK];    // token,k -> expert
__device__ float g_tw[TT*TOPK];    // token,k -> gate weight
__device__ int   g_epos[TT*TOPK];  // token,k -> entry position

// ---------------- SGEMM: C[M,N] = A[M,K] @ B[K,N] + bias, optional relu ----
#define BM 128
#define BN 128
#define BK 8
#define TM 8
#define TN 8

__global__ __launch_bounds__(256, 2)
void sgemm(const float* __restrict__ A, const float* __restrict__ Bm,
           const float* __restrict__ bias, float* __restrict__ C,
           int M, int N, int Kd, int relu)
{
    int m0 = blockIdx.y * BM, n0 = blockIdx.x * BN;
    __shared__ __align__(16) float As[2][BK][BM];
    __shared__ __align__(16) float Bs[2][BK][BN];
    int tid = threadIdx.x;
    int arow = tid >> 1;            // 0..127
    int acol = (tid & 1) * 4;       // 0 or 4
    int brow = tid >> 5;            // 0..7
    int bcol = (tid & 31) * 4;      // 0..124
    int tx = tid & 15, ty = tid >> 4;

    float acc[TM][TN];
#pragma unroll
    for (int i = 0; i < TM; i++)
#pragma unroll
        for (int j = 0; j < TN; j++) acc[i][j] = 0.f;

    const float* arp = A + (size_t)(m0 + arow) * Kd;   // m0+arow < M always here (M mult of 128)
    // tile 0 -> shared
    {
        float4 fa = *(const float4*)(arp + acol);
        As[0][acol+0][arow]=fa.x; As[0][acol+1][arow]=fa.y;
        As[0][acol+2][arow]=fa.z; As[0][acol+3][arow]=fa.w;
        float4 fb = *(const float4*)(Bm + (size_t)brow * N + n0 + bcol);
        *(float4*)&Bs[0][brow][bcol] = fb;
    }
    __syncthreads();

    int nk = Kd / BK;
    for (int t = 0; t < nk; t++) {
        int cur = t & 1, nxt = cur ^ 1;
        float4 ra, rb;
        bool more = (t + 1) < nk;
        if (more) {
            int k0 = (t + 1) * BK;
            ra = *(const float4*)(arp + k0 + acol);
            rb = *(const float4*)(Bm + (size_t)(k0 + brow) * N + n0 + bcol);
        }
#pragma unroll
        for (int k = 0; k < BK; k++) {
            float a[TM], b[TN];
#pragma unroll
            for (int i = 0; i < TM; i++) a[i] = As[cur][k][ty*TM + i];
#pragma unroll
            for (int j = 0; j < TN; j++) b[j] = Bs[cur][k][tx*TN + j];
#pragma unroll
            for (int i = 0; i < TM; i++)
#pragma unroll
                for (int j = 0; j < TN; j++) acc[i][j] += a[i] * b[j];
        }
        if (more) {
            As[nxt][acol+0][arow]=ra.x; As[nxt][acol+1][arow]=ra.y;
            As[nxt][acol+2][arow]=ra.z; As[nxt][acol+3][arow]=ra.w;
            *(float4*)&Bs[nxt][brow][bcol] = rb;
        }
        __syncthreads();
    }
#pragma unroll
    for (int i = 0; i < TM; i++) {
        float* crow = C + (size_t)(m0 + ty*TM + i) * N + n0;
#pragma unroll
        for (int j = 0; j < TN; j += 4) {
            int c = tx*TN + j;
            float4 v;
            v.x = acc[i][j+0] + bias[n0 + c + 0];
            v.y = acc[i][j+1] + bias[n0 + c + 1];
            v.z = acc[i][j+2] + bias[n0 + c + 2];
            v.w = acc[i][j+3] + bias[n0 + c + 3];
            if (relu) { v.x = fmaxf(v.x,0.f); v.y = fmaxf(v.y,0.f);
                        v.z = fmaxf(v.z,0.f); v.w = fmaxf(v.w,0.f); }
            *(float4*)(crow + c) = v;
        }
    }
}

// ---------------- MoE segmented GEMM (per-expert, gathered rows) ----------
// indirect=1: A row = Aall[g_tok[entry]] (layer1), else A row = Aall[entry].
// C row = entry. Bm/bias offset by expert. Guards on segment count.
__global__ __launch_bounds__(256, 2)
void moe_gemm(const float* __restrict__ Aall, const float* __restrict__ Ball,
              const float* __restrict__ ball, float* __restrict__ C,
              int N, int Kd, int relu, int indirect)
{
    int e = blockIdx.z;
    int cnt = g_cnt[e], base = g_base[e];
    int m0 = blockIdx.y * BM;
    if (m0 >= cnt) return;
    int n0 = blockIdx.x * BN;
    const float* Bm = Ball + (size_t)e * Kd * N;
    const float* bias = ball + (size_t)e * N;

    __shared__ __align__(16) float As[2][BK][BM];
    __shared__ __align__(16) float Bs[2][BK][BN];
    int tid = threadIdx.x;
    int arow = tid >> 1;
    int acol = (tid & 1) * 4;
    int brow = tid >> 5;
    int bcol = (tid & 31) * 4;
    int tx = tid & 15, ty = tid >> 4;

    float acc[TM][TN];
#pragma unroll
    for (int i = 0; i < TM; i++)
#pragma unroll
        for (int j = 0; j < TN; j++) acc[i][j] = 0.f;

    bool avalid = (m0 + arow) < cnt;
    const float* arp = nullptr;
    if (avalid) {
        int entry = base + m0 + arow;
        int row = indirect ? g_tok[entry] : entry;
        arp = Aall + (size_t)row * Kd;
    }
    {
        float4 fa = make_float4(0.f,0.f,0.f,0.f);
        if (avalid) fa = *(const float4*)(arp + acol);
        As[0][acol+0][arow]=fa.x; As[0][acol+1][arow]=fa.y;
        As[0][acol+2][arow]=fa.z; As[0][acol+3][arow]=fa.w;
        float4 fb = *(const float4*)(Bm + (size_t)brow * N + n0 + bcol);
        *(float4*)&Bs[0][brow][bcol] = fb;
    }
    __syncthreads();

    int nk = Kd / BK;
    for (int t = 0; t < nk; t++) {
        int cur = t & 1, nxt = cur ^ 1;
        float4 ra = make_float4(0.f,0.f,0.f,0.f), rb;
        bool more = (t + 1) < nk;
        if (more) {
            int k0 = (t + 1) * BK;
            if (avalid) ra = *(const float4*)(arp + k0 + acol);
            rb = *(const float4*)(Bm + (size_t)(k0 + brow) * N + n0 + bcol);
        }
#pragma unroll
        for (int k = 0; k < BK; k++) {
            float a[TM], b[TN];
#pragma unroll
            for (int i = 0; i < TM; i++) a[i] = As[cur][k][ty*TM + i];
#pragma unroll
            for (int j = 0; j < TN; j++) b[j] = Bs[cur][k][tx*TN + j];
#pragma unroll
            for (int i = 0; i < TM; i++)
#pragma unroll
                for (int j = 0; j < TN; j++) acc[i][j] += a[i] * b[j];
        }
        if (more) {
            As[nxt][acol+0][arow]=ra.x; As[nxt][acol+1][arow]=ra.y;
            As[nxt][acol+2][arow]=ra.z; As[nxt][acol+3][arow]=ra.w;
            *(float4*)&Bs[nxt][brow][bcol] = rb;
        }
        __syncthreads();
    }
#pragma unroll
    for (int i = 0; i < TM; i++) {
        int r = m0 + ty*TM + i;
        if (r >= cnt) continue;
        float* crow = C + (size_t)(base + r) * N + n0;
#pragma unroll
        for (int j = 0; j < TN; j += 4) {
            int c = tx*TN + j;
            float4 v;
            v.x = acc[i][j+0] + bias[n0 + c + 0];
            v.y = acc[i][j+1] + bias[n0 + c + 1];
            v.z = acc[i][j+2] + bias[n0 + c + 2];
            v.w = acc[i][j+3] + bias[n0 + c + 3];
            if (relu) { v.x = fmaxf(v.x,0.f); v.y = fmaxf(v.y,0.f);
                        v.z = fmaxf(v.z,0.f); v.w = fmaxf(v.w,0.f); }
            *(float4*)(crow + c) = v;
        }
    }
}

// ---------------- flash attention (fp32, hd=64, no mask) ------------------
// grid (S/64, H, B), 64 threads, 1 thread per query row, online softmax.
__global__ __launch_bounds__(64)
void attn_kernel(const float* __restrict__ Qm, const float* __restrict__ Km,
                 const float* __restrict__ Vm, float* __restrict__ Om)
{
    int b = blockIdx.z, h = blockIdx.y;
    int tid = threadIdx.x;
    int q = blockIdx.x * 64 + tid;
    __shared__ __align__(16) float Ks[64][64];
    __shared__ __align__(16) float Vs[64][64];
    size_t hoff = (size_t)h * HDIM;
    const float* qp = Qm + ((size_t)b*SS + q) * DD + hoff;

    float qr[64];
#pragma unroll
    for (int d = 0; d < 64; d += 4) {
        float4 f = *(const float4*)(qp + d);
        qr[d]=f.x*0.125f; qr[d+1]=f.y*0.125f; qr[d+2]=f.z*0.125f; qr[d+3]=f.w*0.125f;
    }
    float o[64];
#pragma unroll
    for (int d = 0; d < 64; d++) o[d] = 0.f;
    float m = -1e30f, l = 0.f;

    int lrow = tid >> 4;           // 0..3
    int lcol = (tid & 15) * 4;     // 0..60

    for (int kt = 0; kt < SS; kt += 64) {
        const float* kb = Km + ((size_t)b*SS + kt) * DD + hoff;
        const float* vb = Vm + ((size_t)b*SS + kt) * DD + hoff;
#pragma unroll
        for (int r = 0; r < 64; r += 4) {
            *(float4*)&Ks[r+lrow][lcol] = *(const float4*)(kb + (size_t)(r+lrow)*DD + lcol);
            *(float4*)&Vs[r+lrow][lcol] = *(const float4*)(vb + (size_t)(r+lrow)*DD + lcol);
        }
        __syncthreads();

#pragma unroll 1
        for (int j0 = 0; j0 < 64; j0 += 32) {
            float s[32];
#pragma unroll 4
            for (int j = 0; j < 32; j++) {
                float acc = 0.f;
#pragma unroll
                for (int d = 0; d < 64; d += 4) {
                    float4 kv = *(const float4*)&Ks[j0+j][d];
                    acc += qr[d]*kv.x + qr[d+1]*kv.y + qr[d+2]*kv.z + qr[d+3]*kv.w;
                }
                s[j] = acc;
            }
            float mn = m;
#pragma unroll
            for (int j = 0; j < 32; j++) mn = fmaxf(mn, s[j]);
            float corr = __expf(m - mn);
            m = mn;
            l *= corr;
#pragma unroll
            for (int d = 0; d < 64; d++) o[d] *= corr;
#pragma unroll 4
            for (int j = 0; j < 32; j++) {
                float p = __expf(s[j] - mn);
                l += p;
#pragma unroll
                for (int d = 0; d < 64; d += 4) {
                    float4 vv = *(const float4*)&Vs[j0+j][d];
                    o[d]   += p*vv.x; o[d+1] += p*vv.y;
                    o[d+2] += p*vv.z; o[d+3] += p*vv.w;
                }
            }
        }
        __syncthreads();
    }
    float inv = 1.f / l;
    float* op = Om + ((size_t)b*SS + q) * DD + hoff;
#pragma unroll
    for (int d = 0; d < 64; d += 4) {
        float4 f; f.x=o[d]*inv; f.y=o[d+1]*inv; f.z=o[d+2]*inv; f.w=o[d+3]*inv;
        *(float4*)(op + d) = f;
    }
}

// ---------------- residual + layernorm ------------------------------------
__global__ __launch_bounds__(256)
void add_ln_kernel(const float* __restrict__ A, const float* __restrict__ R,
                   const float* __restrict__ g, const float* __restrict__ bt,
                   float* __restrict__ out)
{
    __shared__ float sh[16];
    int t = blockIdx.x;
    int d0 = threadIdx.x * 4;
    float4 a = *(const float4*)(A + (size_t)t*DD + d0);
    float4 r = *(const float4*)(R + (size_t)t*DD + d0);
    float4 v = make_float4(a.x+r.x, a.y+r.y, a.z+r.z, a.w+r.w);
    float sm = v.x+v.y+v.z+v.w;
    float sq = v.x*v.x + v.y*v.y + v.z*v.z + v.w*v.w;
#pragma unroll
    for (int o = 16; o; o >>= 1) { sm += __shfl_xor_sync(~0u, sm, o); sq += __shfl_xor_sync(~0u, sq, o); }
    int w = threadIdx.x >> 5;
    if ((threadIdx.x & 31) == 0) { sh[w] = sm; sh[8+w] = sq; }
    __syncthreads();
    if (threadIdx.x < 8) {
        sm = sh[threadIdx.x]; sq = sh[8 + threadIdx.x];
#pragma unroll
        for (int o = 4; o; o >>= 1) { sm += __shfl_xor_sync(0xffu, sm, o); sq += __shfl_xor_sync(0xffu, sq, o); }
        if (threadIdx.x == 0) { sh[0] = sm; sh[8] = sq; }
    }
    __syncthreads();
    float mean = sh[0] * (1.f/DD);
    float var  = sh[8] * (1.f/DD) - mean*mean;
    float rs = rsqrtf(var + 1e-5f);
    float4 gg = *(const float4*)(g + d0);
    float4 bb = *(const float4*)(bt + d0);
    float4 ov;
    ov.x = (v.x-mean)*rs*gg.x + bb.x;
    ov.y = (v.y-mean)*rs*gg.y + bb.y;
    ov.z = (v.z-mean)*rs*gg.z + bb.z;
    ov.w = (v.w-mean)*rs*gg.w + bb.w;
    *(float4*)(out + (size_t)t*DD + d0) = ov;
}

// ---------------- MoE combine + final layernorm ---------------------------
__global__ __launch_bounds__(256)
void combine_ln_kernel(const float* __restrict__ X, const float* __restrict__ Y,
                       const float* __restrict__ g, const float* __restrict__ bt,
                       float* __restrict__ out)
{
    __shared__ float sh[16];
    int t = blockIdx.x;
    int e0 = g_epos[t*2+0], e1 = g_epos[t*2+1];
    float w0 = g_tw[t*2+0], w1 = g_tw[t*2+1];
    int d0 = threadIdx.x * 4;
    float4 x = *(const float4*)(X + (size_t)t*DD + d0);
    float4 y0 = *(const float4*)(Y + (size_t)e0*DD + d0);
    float4 y1 = *(const float4*)(Y + (size_t)e1*DD + d0);
    float4 v;
    v.x = x.x + w0*y0.x + w1*y1.x;
    v.y = x.y + w0*y0.y + w1*y1.y;
    v.z = x.z + w0*y0.z + w1*y1.z;
    v.w = x.w + w0*y0.w + w1*y1.w;
    float sm = v.x+v.y+v.z+v.w;
    float sq = v.x*v.x + v.y*v.y + v.z*v.z + v.w*v.w;
#pragma unroll
    for (int o = 16; o; o >>= 1) { sm += __shfl_xor_sync(~0u, sm, o); sq += __shfl_xor_sync(~0u, sq, o); }
    int w = threadIdx.x >> 5;
    if ((threadIdx.x & 31) == 0) { sh[w] = sm; sh[8+w] = sq; }
    __syncthreads();
    if (threadIdx.x < 8) {
        sm = sh[threadIdx.x]; sq = sh[8 + threadIdx.x];
#pragma unroll
        for (int o = 4; o; o >>= 1) { sm += __shfl_xor_sync(0xffu, sm, o); sq += __shfl_xor_sync(0xffu, sq, o); }
        if (threadIdx.x == 0) { sh[0] = sm; sh[8] = sq; }
    }
    __syncthreads();
    float mean = sh[0] * (1.f/DD);
    float var  = sh[8] * (1.f/DD) - mean*mean;
    float rs = rsqrtf(var + 1e-5f);
    float4 gg = *(const float4*)(g + d0);
    float4 bb = *(const float4*)(bt + d0);
    float4 ov;
    ov.x = (v.x-mean)*rs*gg.x + bb.x;
    ov.y = (v.y-mean)*rs*gg.y + bb.y;
    ov.z = (v.z-mean)*rs*gg.z + bb.z;
    ov.w = (v.w-mean)*rs*gg.w + bb.w;
    *(float4*)(out + (size_t)t*DD + d0) = ov;
}

// ---------------- router / bookkeeping ------------------------------------
__global__ void zero_cnt_kernel() {
    if (threadIdx.x < EE) g_cnt[threadIdx.x] = 0;
}

__global__ __launch_bounds__(256)
void router_kernel(const float* __restrict__ X, const float* __restrict__ rw,
                   const float* __restrict__ rb)
{
    int warp = (blockIdx.x * blockDim.x + threadIdx.x) >> 5;
    int lane = threadIdx.x & 31;
    if (warp >= TT) return;
    const float* xr = X + (size_t)warp * DD;
    float acc[EE];
#pragma unroll
    for (int e = 0; e < EE; e++) acc[e] = 0.f;
    for (int d = lane; d < DD; d += 32) {
        float xv = xr[d];
        const float* wrow = rw + (size_t)d * EE;
#pragma unroll
        for (int e = 0; e < EE; e++) acc[e] += xv * wrow[e];
    }
#pragma unroll
    for (int e = 0; e < EE; e++)
#pragma unroll
        for (int o = 16; o; o >>= 1) acc[e] += __shfl_xor_sync(~0u, acc[e], o);
    if (lane == 0) {
        float logits[EE], p[EE];
        float mx = -1e30f;
#pragma unroll
        for (int e = 0; e < EE; e++) { logits[e] = acc[e] + rb[e]; mx = fmaxf(mx, logits[e]); }
        float se = 0.f;
#pragma unroll
        for (int e = 0; e < EE; e++) { p[e] = __expf(logits[e] - mx); se += p[e]; }
        float inv = 1.f / se;
#pragma unroll
        for (int e = 0; e < EE; e++) p[e] *= inv;
        int i0 = 0;
#pragma unroll
        for (int e = 1; e < EE; e++) if (p[e] > p[i0]) i0 = e;
        int i1 = (i0 == 0) ? 1 : 0;
#pragma unroll
        for (int e = 0; e < EE; e++) if (e != i0 && p[e] > p[i1]) i1 = e;
        float s = p[i0] + p[i1];
        g_te[warp*2+0] = i0; g_te[warp*2+1] = i1;
        g_tw[warp*2+0] = p[i0] / s; g_tw[warp*2+1] = p[i1] / s;
        atomicAdd(&g_cnt[i0], 1);
        atomicAdd(&g_cnt[i1], 1);
    }
}

__global__ void scan_kernel() {
    if (threadIdx.x == 0) {
        int b = 0;
        for (int e = 0; e < EE; e++) { g_base[e] = b; g_cur[e] = b; b += g_cnt[e]; }
    }
}

__global__ __launch_bounds__(256)
void place_kernel() {
    int t = blockIdx.x * blockDim.x + threadIdx.x;
    if (t >= TT) return;
#pragma unroll
    for (int k = 0; k < TOPK; k++) {
        int e = g_te[t*2+k];
        int pos = atomicAdd(&g_cur[e], 1);
        g_tok[pos] = t;
        g_epos[t*2+k] = pos;
    }
}

// ---------------- launcher -------------------------------------------------
extern "C" void kernel_launch(void* const* d_in, const int* in_sizes, int n_in,
                              void* d_out, int out_size)
{
    const float* tgt   = (const float*)d_in[0];
    const float* mem   = (const float*)d_in[1];
    const float* sa_wq = (const float*)d_in[2];  const float* sa_bq = (const float*)d_in[3];
    const float* sa_wk = (const float*)d_in[4];  const float* sa_bk = (const float*)d_in[5];
    const float* sa_wv = (const float*)d_in[6];  const float* sa_bv = (const float*)d_in[7];
    const float* sa_wo = (const float*)d_in[8];  const float* sa_bo = (const float*)d_in[9];
    const float* ca_wq = (const float*)d_in[10]; const float* ca_bq = (const float*)d_in[11];
    const float* ca_wk = (const float*)d_in[12]; const float* ca_bk = (const float*)d_in[13];
    const float* ca_wv = (const float*)d_in[14]; const float* ca_bv = (const float*)d_in[15];
    const float* ca_wo = (const float*)d_in[16]; const float* ca_bo = (const float*)d_in[17];
    const float* r_w   = (const float*)d_in[18]; const float* r_b   = (const float*)d_in[19];
    const float* e_w1  = (const float*)d_in[20]; const float* e_b1  = (const float*)d_in[21];
    const float* e_w2  = (const float*)d_in[22]; const float* e_b2  = (const float*)d_in[23];
    const float* n1_g  = (const float*)d_in[24]; const float* n1_b  = (const float*)d_in[25];
    const float* n2_g  = (const float*)d_in[26]; const float* n2_b  = (const float*)d_in[27];
    const float* n3_g  = (const float*)d_in[28]; const float* n3_b  = (const float*)d_in[29];
    float* out = (float*)d_out;

    dim3 gproj(DD/BN, TT/BM);      // (8, 64)
    dim3 gattn(SS/64, HH, BB);     // (32, 16, 4)

    // ---- self-attention block ----
    sgemm<<<gproj, 256>>>(tgt, sa_wq, sa_bq, g_q, TT, DD, DD, 0);
    sgemm<<<gproj, 256>>>(tgt, sa_wk, sa_bk, g_k, TT, DD, DD, 0);
    sgemm<<<gproj, 256>>>(tgt, sa_wv, sa_bv, g_v, TT, DD, DD, 0);
    attn_kernel<<<gattn, 64>>>(g_q, g_k, g_v, g_att);
    sgemm<<<gproj, 256>>>(g_att, sa_wo, sa_bo, g_tmp, TT, DD, DD, 0);
    add_ln_kernel<<<TT, 256>>>(tgt, g_tmp, n1_g, n1_b, g_x1);

    // ---- cross-attention block ----
    sgemm<<<gproj, 256>>>(g_x1, ca_wq, ca_bq, g_q, TT, DD, DD, 0);
    sgemm<<<gproj, 256>>>(mem,  ca_wk, ca_bk, g_k, TT, DD, DD, 0);
    sgemm<<<gproj, 256>>>(mem,  ca_wv, ca_bv, g_v, TT, DD, DD, 0);
    attn_kernel<<<gattn, 64>>>(g_q, g_k, g_v, g_att);
    sgemm<<<gproj, 256>>>(g_att, ca_wo, ca_bo, g_tmp, TT, DD, DD, 0);
    add_ln_kernel<<<TT, 256>>>(g_x1, g_tmp, n2_g, n2_b, g_x2);

    // ---- sparse MoE ----
    zero_cnt_kernel<<<1, 32>>>();
    router_kernel<<<TT/8, 256>>>(g_x2, r_w, r_b);
    scan_kernel<<<1, 32>>>();
    place_kernel<<<TT/256, 256>>>();
    moe_gemm<<<dim3(HID/BN, TT/BM, EE), 256>>>(g_x2, e_w1, e_b1, g_hid, HID, DD, 1, 1);
    moe_gemm<<<dim3(DD/BN,  TT/BM, EE), 256>>>(g_hid, e_w2, e_b2, g_y, DD, HID, 0, 0);
    combine_ln_kernel<<<TT, 256>>>(g_x2, g_y, n3_g, n3_b, out);
}